// round 17
// baseline (speedup 1.0000x reference)
#include <cuda_runtime.h>
#include <cuda_fp16.h>
#include <cstdint>

#define DD 128
#define NMAX 100000
#define EMAX 1600000
#define RESC 0.2f
#define LNEPS 1e-5f

// ---------------- scratch (static device globals; no allocs allowed) --------
__device__ __half g_t[NMAX * DD];      // GEMM input (LN'd features), fp16
__device__ __half g_xw[NMAX * DD];     // GEMM output (pre-aggregation), fp16
__device__ __half g_f16[NMAX * DD];    // in_feat fp16 (residual)
__device__ __half g_w1t[DD * DD];      // W1^T fp16  [n][k]
__device__ __half g_w2t[DD * DD];      // W2^T fp16  [n][k]
__device__ float  g_rout[NMAX];
__device__ float  g_rin[NMAX];
__device__ unsigned long long g_blob[NMAX + 128];  // deg ints + scan states
__device__ int    g_rowptr[NMAX + 1];
__device__ int    g_cursor[NMAX];
__device__ int    g_csrsrc[EMAX];

// ---------------- fused prep: degree + weight transpose + feat->fp16 --------
__global__ void prep_kernel(const int* __restrict__ src, const int* __restrict__ dst,
                            int* __restrict__ dout, int* __restrict__ din,
                            const float* __restrict__ W1, const float* __restrict__ W2,
                            __half* __restrict__ W1t, __half* __restrict__ W2t,
                            const float* __restrict__ feat, __half* __restrict__ feat16,
                            int e, int n, int gridE) {
    int b = blockIdx.x;
    if (b < gridE) {
        int i = b * 256 + threadIdx.x;
        if (i < e) {
            atomicAdd(dout + src[i], 1);
            atomicAdd(din + dst[i], 1);
        }
    } else if (b < gridE + 128) {
        int idx = (b - gridE) * 256 + threadIdx.x;
        int which = idx >> 14;
        int i = idx & 16383;
        int nrow = i >> 7;
        int k = i & 127;
        const float* W = which ? W2 : W1;
        __half* Wt = which ? W2t : W1t;
        Wt[nrow * DD + k] = __float2half_rn(__ldg(W + k * DD + nrow));
    } else {
        int i = (b - gridE - 128) * 256 + threadIdx.x;
        if (i < n * 16) {
            const float4* fp = (const float4*)feat + (size_t)i * 2;
            float4 f0 = __ldg(fp);
            float4 f1 = __ldg(fp + 1);
            uint4 u;
            *(__half2*)&u.x = __floats2half2_rn(f0.x, f0.y);
            *(__half2*)&u.y = __floats2half2_rn(f0.z, f0.w);
            *(__half2*)&u.z = __floats2half2_rn(f1.x, f1.y);
            *(__half2*)&u.w = __floats2half2_rn(f1.z, f1.w);
            ((uint4*)feat16)[i] = u;
        }
    }
}

// ---------------- single-pass decoupled-lookback scan ------------------------
__global__ __launch_bounds__(256) void scan_lookback_kernel(
    const int* __restrict__ degin, const int* __restrict__ degout,
    unsigned long long* __restrict__ state,
    int* __restrict__ rowptr, int* __restrict__ cursor,
    float* __restrict__ rout, float* __restrict__ rin,
    int n, int e)
{
    __shared__ int wsum[8];
    __shared__ int sExcl;
    int b = blockIdx.x;
    int t = threadIdx.x;
    int lane = t & 31, wid = t >> 5;
    int base = b * 1024 + t * 4;

    int v0 = (base + 0 < n) ? degin[base + 0] : 0;
    int v1 = (base + 1 < n) ? degin[base + 1] : 0;
    int v2 = (base + 2 < n) ? degin[base + 2] : 0;
    int v3 = (base + 3 < n) ? degin[base + 3] : 0;
    int tsum = v0 + v1 + v2 + v3;

    int x = tsum;
#pragma unroll
    for (int o = 1; o < 32; o <<= 1) {
        int y = __shfl_up_sync(0xFFFFFFFFu, x, o);
        if (lane >= o) x += y;
    }
    if (lane == 31) wsum[wid] = x;
    __syncthreads();

    if (wid == 0) {
        int w = (lane < 8) ? wsum[lane] : 0;
        int orig = w;
#pragma unroll
        for (int o = 1; o < 8; o <<= 1) {
            int y = __shfl_up_sync(0xFFFFFFFFu, w, o);
            if (lane >= o) w += y;
        }
        if (lane < 8) wsum[lane] = w - orig;
        int total = __shfl_sync(0xFFFFFFFFu, w, 7);

        if (lane == 0) {
            unsigned long long pub =
                ((unsigned long long)(b == 0 ? 2u : 1u) << 32) | (unsigned)total;
            atomicExch(&state[b], pub);
        }

        int excl = 0;
        if (b > 0) {
            int p = b - 1;
            while (true) {
                int idx = p - lane;
                unsigned long long v;
                if (idx >= 0) {
                    do { v = atomicAdd(&state[idx], 0ULL); } while ((v >> 32) == 0);
                } else {
                    v = (2ULL << 32);
                }
                unsigned flag = (unsigned)(v >> 32);
                int val = (int)(v & 0xFFFFFFFFu);
                unsigned pmask = __ballot_sync(0xFFFFFFFFu, flag == 2u);
                int c;
                if (pmask) {
                    int L = __ffs(pmask) - 1;
                    c = (lane <= L) ? val : 0;
                } else {
                    c = val;
                }
#pragma unroll
                for (int o = 16; o > 0; o >>= 1) c += __shfl_xor_sync(0xFFFFFFFFu, c, o);
                excl += c;
                if (pmask) break;
                p -= 32;
            }
            if (lane == 0)
                atomicExch(&state[b], (2ULL << 32) | (unsigned)(excl + total));
        }
        if (lane == 0) sExcl = excl;
    }
    __syncthreads();

    int texcl = wsum[wid] + x - tsum + sExcl;
    int run = texcl;
    int dv[4] = {v0, v1, v2, v3};
#pragma unroll
    for (int i = 0; i < 4; i++) {
        int idx = base + i;
        if (idx < n) {
            rowptr[idx] = run;
            cursor[idx] = run;
            rout[idx] = rsqrtf((float)max(degout[idx], 1));
            rin[idx]  = rsqrtf((float)max(dv[i], 1));
        }
        run += dv[i];
    }
    if (b == 0 && t == 0) rowptr[n] = e;
}

__global__ void csr_fill_kernel(const int* __restrict__ src, const int* __restrict__ dst,
                                int* __restrict__ cursor, int* __restrict__ csr, int e) {
    int i = blockIdx.x * blockDim.x + threadIdx.x;
    if (i < e) {
        int p = atomicAdd(cursor + dst[i], 1);
        csr[p] = src[i];
    }
}

// ---------------- common GEMM pieces -----------------------------------------
#define SWH 136
#define SAH2 24

__device__ __forceinline__ uint32_t smem_u32(const void* p) {
    return (uint32_t)__cvta_generic_to_shared(p);
}

// ---------------- GEMM A (conv1): fp32 A, rout folded into fp16 staging ------
__global__ __launch_bounds__(256) void gemm_f32in_kernel(
    const float* __restrict__ A, const __half* __restrict__ Wt,
    const float* __restrict__ rs, __half* __restrict__ C, int n)
{
    __shared__ __half sW[128 * SWH];
    __shared__ __half sA[2][64 * SAH2];

    int tid = threadIdx.x;
    int lane = tid & 31;
    int wrp = tid >> 5;
    int wm = wrp & 1;
    int wn = wrp >> 1;
    int tig = lane & 3;
    int gid = lane >> 2;

#pragma unroll
    for (int q = 0; q < 8; q++) {
        int idx = q * 256 + tid;
        int wr = idx >> 4;
        int kb = idx & 15;
        *(uint4*)&sW[wr * SWH + kb * 8] = *(const uint4*)(Wt + wr * DD + kb * 8);
    }

    int quad = lane >> 3, wi = lane & 7;
    uint32_t aAddr[2][2];
#pragma unroll
    for (int buf = 0; buf < 2; buf++)
#pragma unroll
        for (int mt = 0; mt < 2; mt++) {
            int ar = wm * 32 + mt * 16 + wi + (quad & 1) * 8;
            aAddr[buf][mt] = smem_u32(&sA[buf][ar * SAH2 + (quad >> 1) * 8]);
        }
    int wi2 = lane & 7, sel = (lane >> 3) & 1;
    uint32_t bAddr[4];
#pragma unroll
    for (int nt = 0; nt < 4; nt++) {
        int br = wn * 32 + nt * 8 + wi2;
        bAddr[nt] = smem_u32(&sW[br * SWH + sel * 8]);
    }

    int arow = tid >> 2;
    int ak = (tid & 3) << 2;
    int nTiles = (n + 63) >> 6;

    for (int tile = blockIdx.x; tile < nTiles; tile += gridDim.x) {
        int row0 = tile * 64;
        int grow = row0 + arow;
        bool rok = grow < n;
        float sc = 1.0f;
        if (rok) sc = __ldg(rs + grow);
        const float* Ap = A + (size_t)grow * DD + ak;

        uint2 av = make_uint2(0, 0);
        if (rok) {
            float4 f = *(const float4*)Ap;
            *(__half2*)&av.x = __floats2half2_rn(f.x * sc, f.y * sc);
            *(__half2*)&av.y = __floats2half2_rn(f.z * sc, f.w * sc);
        }
        *(uint2*)&sA[0][arow * SAH2 + ak] = av;
        __syncthreads();

        float acc[2][4][4];
#pragma unroll
        for (int i = 0; i < 2; i++)
#pragma unroll
            for (int j = 0; j < 4; j++)
#pragma unroll
                for (int k = 0; k < 4; k++) acc[i][j][k] = 0.0f;

#pragma unroll
        for (int s = 0; s < 8; s++) {
            int cur = s & 1;
            if (s < 7) {
                av = make_uint2(0, 0);
                if (rok) {
                    float4 f = *(const float4*)(Ap + (s + 1) * 16);
                    *(__half2*)&av.x = __floats2half2_rn(f.x * sc, f.y * sc);
                    *(__half2*)&av.y = __floats2half2_rn(f.z * sc, f.w * sc);
                }
            }

            uint32_t af[2][4];
#pragma unroll
            for (int mt = 0; mt < 2; mt++) {
                asm volatile(
                    "ldmatrix.sync.aligned.m8n8.x4.shared.b16 {%0,%1,%2,%3}, [%4];"
                    : "=r"(af[mt][0]), "=r"(af[mt][1]), "=r"(af[mt][2]), "=r"(af[mt][3])
                    : "r"(aAddr[cur][mt]));
            }
            uint32_t bf[4][2];
            uint32_t boff = (uint32_t)s * 32;
#pragma unroll
            for (int nt = 0; nt < 4; nt++) {
                asm volatile(
                    "ldmatrix.sync.aligned.m8n8.x2.shared.b16 {%0,%1}, [%2];"
                    : "=r"(bf[nt][0]), "=r"(bf[nt][1])
                    : "r"(bAddr[nt] + boff));
            }
#pragma unroll
            for (int nt = 0; nt < 4; nt++) {
#pragma unroll
                for (int mt = 0; mt < 2; mt++) {
                    asm volatile(
                        "mma.sync.aligned.m16n8k16.row.col.f32.f16.f16.f32 "
                        "{%0,%1,%2,%3}, {%4,%5,%6,%7}, {%8,%9}, {%0,%1,%2,%3};"
                        : "+f"(acc[mt][nt][0]), "+f"(acc[mt][nt][1]),
                          "+f"(acc[mt][nt][2]), "+f"(acc[mt][nt][3])
                        : "r"(af[mt][0]), "r"(af[mt][1]), "r"(af[mt][2]), "r"(af[mt][3]),
                          "r"(bf[nt][0]), "r"(bf[nt][1]));
                }
            }

            if (s < 7) {
                int nb = cur ^ 1;
                *(uint2*)&sA[nb][arow * SAH2 + ak] = av;
                __syncthreads();
            }
        }

#pragma unroll
        for (int mt = 0; mt < 2; mt++) {
            int r0 = row0 + wm * 32 + mt * 16 + gid;
            int r1 = r0 + 8;
#pragma unroll
            for (int nt = 0; nt < 4; nt++) {
                int col = wn * 32 + nt * 8 + tig * 2;
                if (r0 < n)
                    *(__half2*)(C + (size_t)r0 * DD + col) =
                        __floats2half2_rn(acc[mt][nt][0], acc[mt][nt][1]);
                if (r1 < n)
                    *(__half2*)(C + (size_t)r1 * DD + col) =
                        __floats2half2_rn(acc[mt][nt][2], acc[mt][nt][3]);
            }
        }
        __syncthreads();  // all LDSM done before next tile's stage-0 store
    }
}

// ---------------- GEMM B (conv2/3): fp16 A, cp.async 3-stage ring ------------
__device__ __forceinline__ void cpa8(uint32_t dst, const __half* src) {
    asm volatile("cp.async.ca.shared.global [%0], [%1], 8;"
                 :: "r"(dst), "l"(src) : "memory");
}
__device__ __forceinline__ void cpa_commit() {
    asm volatile("cp.async.commit_group;" ::: "memory");
}
__device__ __forceinline__ void cpa_wait1() {
    asm volatile("cp.async.wait_group 1;" ::: "memory");
}
__device__ __forceinline__ void cpa_wait0() {
    asm volatile("cp.async.wait_group 0;" ::: "memory");
}

__global__ __launch_bounds__(256) void gemm_f16_kernel(
    const __half* __restrict__ A, const __half* __restrict__ Wt,
    __half* __restrict__ C, int n)
{
    __shared__ __half sW[128 * SWH];
    __shared__ __half sA[3][64 * SAH2];

    int tid = threadIdx.x;
    int lane = tid & 31;
    int wrp = tid >> 5;
    int wm = wrp & 1;
    int wn = wrp >> 1;
    int tig = lane & 3;
    int gid = lane >> 2;

#pragma unroll
    for (int q = 0; q < 8; q++) {
        int idx = q * 256 + tid;
        int wr = idx >> 4;
        int kb = idx & 15;
        *(uint4*)&sW[wr * SWH + kb * 8] = *(const uint4*)(Wt + wr * DD + kb * 8);
    }

    int quad = lane >> 3, wi = lane & 7;
    uint32_t aAddr[3][2];
#pragma unroll
    for (int buf = 0; buf < 3; buf++)
#pragma unroll
        for (int mt = 0; mt < 2; mt++) {
            int ar = wm * 32 + mt * 16 + wi + (quad & 1) * 8;
            aAddr[buf][mt] = smem_u32(&sA[buf][ar * SAH2 + (quad >> 1) * 8]);
        }
    int wi2 = lane & 7, sel = (lane >> 3) & 1;
    uint32_t bAddr[4];
#pragma unroll
    for (int nt = 0; nt < 4; nt++) {
        int br = wn * 32 + nt * 8 + wi2;
        bAddr[nt] = smem_u32(&sW[br * SWH + sel * 8]);
    }

    int arow = tid >> 2;
    int ak = (tid & 3) << 2;
    uint32_t dstA[3];
#pragma unroll
    for (int buf = 0; buf < 3; buf++)
        dstA[buf] = smem_u32(&sA[buf][arow * SAH2 + ak]);

    int nTiles = (n + 63) >> 6;

    for (int tile = blockIdx.x; tile < nTiles; tile += gridDim.x) {
        int row0 = tile * 64;
        int grow = row0 + arow;
        int growc = grow < n ? grow : (n - 1);
        const __half* Ap = A + (size_t)growc * DD + ak;

        __syncthreads();
        cpa8(dstA[0], Ap);       cpa_commit();
        cpa8(dstA[1], Ap + 16);  cpa_commit();

        float acc[2][4][4];
#pragma unroll
        for (int i = 0; i < 2; i++)
#pragma unroll
            for (int j = 0; j < 4; j++)
#pragma unroll
                for (int k = 0; k < 4; k++) acc[i][j][k] = 0.0f;

#pragma unroll
        for (int s = 0; s < 8; s++) {
            // stage-s group must be COMPLETE before reading its buffer.
            // s<=6: one younger group may stay in flight; s==7: stage-7 group
            // is the newest, so drain fully (R15/R16 bug: wait1 here raced).
            if (s < 7) cpa_wait1(); else cpa_wait0();
            __syncthreads();
            if (s < 6) {
                cpa8(dstA[(s + 2) % 3], Ap + (s + 2) * 16);
                cpa_commit();
            }

            uint32_t af[2][4];
#pragma unroll
            for (int mt = 0; mt < 2; mt++) {
                asm volatile(
                    "ldmatrix.sync.aligned.m8n8.x4.shared.b16 {%0,%1,%2,%3}, [%4];"
                    : "=r"(af[mt][0]), "=r"(af[mt][1]), "=r"(af[mt][2]), "=r"(af[mt][3])
                    : "r"(aAddr[s % 3][mt]));
            }
            uint32_t bf[4][2];
            uint32_t boff = (uint32_t)s * 32;
#pragma unroll
            for (int nt = 0; nt < 4; nt++) {
                asm volatile(
                    "ldmatrix.sync.aligned.m8n8.x2.shared.b16 {%0,%1}, [%2];"
                    : "=r"(bf[nt][0]), "=r"(bf[nt][1])
                    : "r"(bAddr[nt] + boff));
            }
#pragma unroll
            for (int nt = 0; nt < 4; nt++) {
#pragma unroll
                for (int mt = 0; mt < 2; mt++) {
                    asm volatile(
                        "mma.sync.aligned.m16n8k16.row.col.f32.f16.f16.f32 "
                        "{%0,%1,%2,%3}, {%4,%5,%6,%7}, {%8,%9}, {%0,%1,%2,%3};"
                        : "+f"(acc[mt][nt][0]), "+f"(acc[mt][nt][1]),
                          "+f"(acc[mt][nt][2]), "+f"(acc[mt][nt][3])
                        : "r"(af[mt][0]), "r"(af[mt][1]), "r"(af[mt][2]), "r"(af[mt][3]),
                          "r"(bf[nt][0]), "r"(bf[nt][1]));
                }
            }
        }

#pragma unroll
        for (int mt = 0; mt < 2; mt++) {
            int r0 = row0 + wm * 32 + mt * 16 + gid;
            int r1 = r0 + 8;
#pragma unroll
            for (int nt = 0; nt < 4; nt++) {
                int col = wn * 32 + nt * 8 + tig * 2;
                if (r0 < n)
                    *(__half2*)(C + (size_t)r0 * DD + col) =
                        __floats2half2_rn(acc[mt][nt][0], acc[mt][nt][1]);
                if (r1 < n)
                    *(__half2*)(C + (size_t)r1 * DD + col) =
                        __floats2half2_rn(acc[mt][nt][2], acc[mt][nt][3]);
            }
        }
    }
}

// ---------------- fused CSR aggregate: half-warp per row, uint4 loads --------
__device__ __forceinline__ void acc_u4(uint4 u, float* a) {
    float2 p0 = __half22float2(*(const __half2*)&u.x);
    float2 p1 = __half22float2(*(const __half2*)&u.y);
    float2 p2 = __half22float2(*(const __half2*)&u.z);
    float2 p3 = __half22float2(*(const __half2*)&u.w);
    a[0] += p0.x; a[1] += p0.y; a[2] += p1.x; a[3] += p1.y;
    a[4] += p2.x; a[5] += p2.y; a[6] += p3.x; a[7] += p3.y;
}

template <bool DO_LN, typename OT>
__global__ void agg_kernel(const int* __restrict__ rowptr, const int* __restrict__ csr,
                           const __half* __restrict__ xw, const float* __restrict__ rin,
                           const float* __restrict__ bias, const __half* __restrict__ feat16,
                           const float* __restrict__ lng, const float* __restrict__ lnb,
                           const float* __restrict__ rout, OT* __restrict__ o, int n)
{
    int row = blockIdx.x * 16 + (threadIdx.x >> 4);
    if (row >= n) return;
    int l16 = threadIdx.x & 15;

    int beg = __ldg(rowptr + row);
    int end = __ldg(rowptr + row + 1);

    const uint4* xwv = (const uint4*)xw + l16;
    float a[8] = {0.f, 0.f, 0.f, 0.f, 0.f, 0.f, 0.f, 0.f};

    int e = beg;
    for (; e + 8 <= end; e += 8) {
        int s[8];
#pragma unroll
        for (int q = 0; q < 8; q++) s[q] = __ldg(csr + e + q);
        uint4 u[8];
#pragma unroll
        for (int q = 0; q < 8; q++) u[q] = __ldg(xwv + (size_t)s[q] * 16);
#pragma unroll
        for (int q = 0; q < 8; q++) acc_u4(u[q], a);
    }
    if (e + 4 <= end) {
        int s[4];
#pragma unroll
        for (int q = 0; q < 4; q++) s[q] = __ldg(csr + e + q);
        uint4 u[4];
#pragma unroll
        for (int q = 0; q < 4; q++) u[q] = __ldg(xwv + (size_t)s[q] * 16);
#pragma unroll
        for (int q = 0; q < 4; q++) acc_u4(u[q], a);
        e += 4;
    }
    if (e + 2 <= end) {
        int s0 = __ldg(csr + e), s1 = __ldg(csr + e + 1);
        uint4 u0 = __ldg(xwv + (size_t)s0 * 16);
        uint4 u1 = __ldg(xwv + (size_t)s1 * 16);
        acc_u4(u0, a);
        acc_u4(u1, a);
        e += 2;
    }
    if (e < end) {
        int s0 = __ldg(csr + e);
        acc_u4(__ldg(xwv + (size_t)s0 * 16), a);
    }

    uint4 uf = __ldg((const uint4*)feat16 + (size_t)row * 16 + l16);
    float f[8];
    {
        float2 p0 = __half22float2(*(const __half2*)&uf.x);
        float2 p1 = __half22float2(*(const __half2*)&uf.y);
        float2 p2 = __half22float2(*(const __half2*)&uf.z);
        float2 p3 = __half22float2(*(const __half2*)&uf.w);
        f[0] = p0.x; f[1] = p0.y; f[2] = p1.x; f[3] = p1.y;
        f[4] = p2.x; f[5] = p2.y; f[6] = p3.x; f[7] = p3.y;
    }

    float s = __ldg(rin + row);
    float4 b0 = ((const float4*)bias)[l16 * 2];
    float4 b1 = ((const float4*)bias)[l16 * 2 + 1];
    float bb[8] = {b0.x, b0.y, b0.z, b0.w, b1.x, b1.y, b1.z, b1.w};
    float h[8];
#pragma unroll
    for (int q = 0; q < 8; q++) h[q] = fmaf(a[q], s, bb[q]) + RESC * f[q];

    if (!DO_LN) {
        float* op = (float*)o + (size_t)row * DD + l16 * 8;
        *(float4*)op = make_float4(h[0], h[1], h[2], h[3]);
        *(float4*)(op + 4) = make_float4(h[4], h[5], h[6], h[7]);
        return;
    }

    float sum = 0.f;
#pragma unroll
    for (int q = 0; q < 8; q++) sum += h[q];
#pragma unroll
    for (int off = 8; off > 0; off >>= 1) sum += __shfl_xor_sync(0xFFFFFFFFu, sum, off);
    float mu = sum * (1.0f / 128.0f);

    float d[8], sq = 0.f;
#pragma unroll
    for (int q = 0; q < 8; q++) { d[q] = h[q] - mu; sq += d[q] * d[q]; }
#pragma unroll
    for (int off = 8; off > 0; off >>= 1) sq += __shfl_xor_sync(0xFFFFFFFFu, sq, off);
    float inv = rsqrtf(sq * (1.0f / 128.0f) + LNEPS);

    float ro = __ldg(rout + row);
    float4 g0 = ((const float4*)lng)[l16 * 2];
    float4 g1 = ((const float4*)lng)[l16 * 2 + 1];
    float4 lb0 = ((const float4*)lnb)[l16 * 2];
    float4 lb1 = ((const float4*)lnb)[l16 * 2 + 1];
    float gg[8] = {g0.x, g0.y, g0.z, g0.w, g1.x, g1.y, g1.z, g1.w};
    float lb[8] = {lb0.x, lb0.y, lb0.z, lb0.w, lb1.x, lb1.y, lb1.z, lb1.w};

    float r[8];
#pragma unroll
    for (int q = 0; q < 8; q++)
        r[q] = fmaxf(fmaf(d[q] * inv, gg[q], lb[q]), 0.0f) * ro;

    uint4 w;
    *(__half2*)&w.x = __floats2half2_rn(r[0], r[1]);
    *(__half2*)&w.y = __floats2half2_rn(r[2], r[3]);
    *(__half2*)&w.z = __floats2half2_rn(r[4], r[5]);
    *(__half2*)&w.w = __floats2half2_rn(r[6], r[7]);
    ((uint4*)((__half*)o + (size_t)row * DD))[l16] = w;
}

// ---------------- launch ------------------------------------------------------
extern "C" void kernel_launch(void* const* d_in, const int* in_sizes, int n_in,
                              void* d_out, int out_size)
{
    const int*   src     = (const int*)d_in[0];
    const int*   dst     = (const int*)d_in[1];
    const float* in_feat = (const float*)d_in[2];
    const float* W1      = (const float*)d_in[3];
    const float* b1      = (const float*)d_in[4];
    const float* W2      = (const float*)d_in[5];
    const float* b2      = (const float*)d_in[6];
    const float* ln1g    = (const float*)d_in[7];
    const float* ln1b    = (const float*)d_in[8];
    const float* ln2g    = (const float*)d_in[9];
    const float* ln2b    = (const float*)d_in[10];
    float* out = (float*)d_out;

    int E = in_sizes[0];
    int n = in_sizes[2] / DD;

    __half *t, *xw, *f16, *w1t, *w2t;
    float *rout, *rin;
    unsigned long long* blob;
    int *rowptr, *cursor, *csrsrc;
    cudaGetSymbolAddress((void**)&t,      g_t);
    cudaGetSymbolAddress((void**)&xw,     g_xw);
    cudaGetSymbolAddress((void**)&f16,    g_f16);
    cudaGetSymbolAddress((void**)&w1t,    g_w1t);
    cudaGetSymbolAddress((void**)&w2t,    g_w2t);
    cudaGetSymbolAddress((void**)&rout,   g_rout);
    cudaGetSymbolAddress((void**)&rin,    g_rin);
    cudaGetSymbolAddress((void**)&blob,   g_blob);
    cudaGetSymbolAddress((void**)&rowptr, g_rowptr);
    cudaGetSymbolAddress((void**)&cursor, g_cursor);
    cudaGetSymbolAddress((void**)&csrsrc, g_csrsrc);
    int* degout = (int*)blob;
    int* degin  = degout + NMAX;
    unsigned long long* state = blob + NMAX;

    const int TB = 256;
    int gridE    = (E + TB - 1) / TB;
    int gridF    = (n * 16 + TB - 1) / TB;
    int gridRow  = (n + 15) / 16;
    int nTiles   = (n + 63) / 64;
    int grid1    = nTiles < 444 ? nTiles : 444;  // conv1: 3 CTAs/SM
    int grid23   = nTiles < 592 ? nTiles : 592;  // conv2/3: 4 CTAs/SM
    int gridScan = (n + 1023) / 1024;

    cudaMemsetAsync(blob, 0, (NMAX + 128) * sizeof(unsigned long long));
    prep_kernel<<<gridE + 128 + gridF, TB>>>(src, dst, degout, degin, W1, W2,
                                             w1t, w2t, in_feat, f16, E, n, gridE);
    scan_lookback_kernel<<<gridScan, 256>>>(degin, degout, state, rowptr, cursor,
                                            rout, rin, n, E);
    csr_fill_kernel<<<gridE, TB>>>(src, dst, cursor, csrsrc, E);

    // conv1 (fp32 A, rout in staging — proven numerics)
    gemm_f32in_kernel<<<grid1, TB>>>(in_feat, w1t, rout, xw, n);
    agg_kernel<true, __half><<<gridRow, TB>>>(rowptr, csrsrc, xw, rin, b1, f16,
                                              ln1g, ln1b, rout, t, n);

    // conv2
    gemm_f16_kernel<<<grid23, TB>>>(t, w2t, xw, n);
    agg_kernel<true, __half><<<gridRow, TB>>>(rowptr, csrsrc, xw, rin, b2, f16,
                                              ln2g, ln2b, rout, t, n);

    // conv3
    gemm_f16_kernel<<<grid23, TB>>>(t, w2t, xw, n);
    agg_kernel<false, float><<<gridRow, TB>>>(rowptr, csrsrc, xw, rin, b2, f16,
                                              nullptr, nullptr, nullptr, out, n);
}